// round 7
// baseline (speedup 1.0000x reference)
#include <cuda_runtime.h>
#include <cuda_bf16.h>
#include <mma.h>
#include <cstdint>
#include <math.h>

using namespace nvcuda;

#define NUM_C   10
#define OUT_CH  16
#define BATCH   256
#define KDIM    9216
#define NCOL    160

#define KSPLIT  36
#define KPER    256            /* K per block */
#define KT      16             /* K per stage */
#define NSTG    16
#define NTHR    256
#define LDA     24             /* padded bf16 row (48B): LDSM conflict-free */
#define PSTRIDE (KSPLIT * NCOL)   /* 5760 */

/* partials: [b(256)][ks(36)][n(160)] — per-b contiguous for routing */
__device__ float g_Upart[BATCH * KSPLIT * NCOL];

__device__ __forceinline__ __nv_bfloat16 bhi(float x) { return __float2bfloat16_rn(x); }

__device__ __forceinline__ void load_x_regs(const float4* __restrict__ x4,
                                            int mh, int k0, int tid, float4 rx[2]) {
    #pragma unroll
    for (int j = 0; j < 2; j++) {
        int fid = j * 256 + tid;
        int row = fid >> 2, xq = fid & 3;
        rx[j] = x4[(size_t)(mh * 128 + row) * (KDIM / 4) + (k0 >> 2) + xq];
    }
}
__device__ __forceinline__ void load_w_regs(const float4* __restrict__ w4,
                                            int nh, int k0, int tid,
                                            float4& rw0, float4& rw1) {
    {
        int fid = tid, cl = fid >> 6, rem = fid & 63;
        rw0 = w4[((size_t)(nh * 5 + cl) * KDIM + k0 + (rem >> 2)) * 4 + (rem & 3)];
    }
    if (tid < 64) {
        int fid = 256 + tid, cl = fid >> 6, rem = fid & 63;
        rw1 = w4[((size_t)(nh * 5 + cl) * KDIM + k0 + (rem >> 2)) * 4 + (rem & 3)];
    }
}

__device__ __forceinline__ void conv_w_elem(__nv_bfloat16* Bh, __nv_bfloat16* Bl,
                                            int fid, const float4& rw) {
    int cl = fid >> 6, rem = fid & 63;
    int kloc = rem >> 2, o4 = rem & 3;
    float f[4] = {rw.x, rw.y, rw.z, rw.w};
    #pragma unroll
    for (int e = 0; e < 4; e++) {
        int n_loc = cl * 16 + o4 * 4 + e;
        __nv_bfloat16 h = bhi(f[e]);
        Bh[n_loc * LDA + kloc] = h;
        Bl[n_loc * LDA + kloc] = bhi(f[e] - __bfloat162float(h));
    }
}

/* ============ GEMM: pipelined 3-pass bf16-split wmma, split-K ============ */
__global__ void __launch_bounds__(NTHR, 1)
gemm_kernel(const float* __restrict__ x, const float* __restrict__ w) {
    __shared__ __align__(16) __nv_bfloat16 Ah[2][128 * LDA];
    __shared__ __align__(16) __nv_bfloat16 Al[2][128 * LDA];
    __shared__ __align__(16) __nv_bfloat16 Bh[2][80 * LDA];
    __shared__ __align__(16) __nv_bfloat16 Bl[2][80 * LDA];

    const int tid  = threadIdx.x;
    const int warp = tid >> 5;
    const int ks   = blockIdx.x;
    const int nh   = blockIdx.y;
    const int mh   = blockIdx.z;
    const int kbase = ks * KPER;

    const float4* __restrict__ x4 = (const float4*)x;
    const float4* __restrict__ w4 = (const float4*)w;

    wmma::fragment<wmma::accumulator, 16, 16, 16, float> c[5];
    #pragma unroll
    for (int nt = 0; nt < 5; nt++) wmma::fill_fragment(c[nt], 0.0f);

    float4 rx[2], rw0, rw1;
    const int xrow = tid >> 2;    /* + j*64 */
    const int xq   = tid & 3;

    /* preamble: stage 0 -> buf0, prefetch stage 1 */
    load_x_regs(x4, mh, kbase, tid, rx);
    load_w_regs(w4, nh, kbase, tid, rw0, rw1);
    {
        #pragma unroll
        for (int j = 0; j < 2; j++) {
            float4 v = rx[j];
            float f[4] = {v.x, v.y, v.z, v.w};
            __nv_bfloat16 h[4], l[4];
            #pragma unroll
            for (int e = 0; e < 4; e++) {
                h[e] = bhi(f[e]);
                l[e] = bhi(f[e] - __bfloat162float(h[e]));
            }
            int row = j * 64 + xrow;
            __nv_bfloat162* ph = (__nv_bfloat162*)&Ah[0][row * LDA + xq * 4];
            __nv_bfloat162* pl = (__nv_bfloat162*)&Al[0][row * LDA + xq * 4];
            ph[0] = __halves2bfloat162(h[0], h[1]);
            ph[1] = __halves2bfloat162(h[2], h[3]);
            pl[0] = __halves2bfloat162(l[0], l[1]);
            pl[1] = __halves2bfloat162(l[2], l[3]);
        }
        conv_w_elem(Bh[0], Bl[0], tid, rw0);
        if (tid < 64) conv_w_elem(Bh[0], Bl[0], 256 + tid, rw1);
    }
    load_x_regs(x4, mh, kbase + KT, tid, rx);
    load_w_regs(w4, nh, kbase + KT, tid, rw0, rw1);
    __syncthreads();

    const int m0 = warp * 16;

    #pragma unroll
    for (int s = 0; s < NSTG; s++) {
        const int d = s & 1;

        /* MMA on buffer d (tensor pipe) */
        {
            wmma::fragment<wmma::matrix_a, 16, 16, 16, __nv_bfloat16, wmma::row_major> ah, al;
            wmma::load_matrix_sync(ah, &Ah[d][m0 * LDA], LDA);
            wmma::load_matrix_sync(al, &Al[d][m0 * LDA], LDA);
            wmma::fragment<wmma::matrix_b, 16, 16, 16, __nv_bfloat16, wmma::col_major> bh[5], bl[5];
            #pragma unroll
            for (int nt = 0; nt < 5; nt++) {
                wmma::load_matrix_sync(bh[nt], &Bh[d][nt * 16 * LDA], LDA);
                wmma::load_matrix_sync(bl[nt], &Bl[d][nt * 16 * LDA], LDA);
            }
            #pragma unroll
            for (int nt = 0; nt < 5; nt++) wmma::mma_sync(c[nt], ah, bh[nt], c[nt]);
            #pragma unroll
            for (int nt = 0; nt < 5; nt++) wmma::mma_sync(c[nt], ah, bl[nt], c[nt]);
            #pragma unroll
            for (int nt = 0; nt < 5; nt++) wmma::mma_sync(c[nt], al, bh[nt], c[nt]);
        }

        /* convert stage s+1 into buffer d^1 (ALU pipe, overlaps via warp skew) */
        if (s + 1 < NSTG) {
            const int d2 = d ^ 1;
            #pragma unroll
            for (int j = 0; j < 2; j++) {
                float4 v = rx[j];
                float f[4] = {v.x, v.y, v.z, v.w};
                __nv_bfloat16 h[4], l[4];
                #pragma unroll
                for (int e = 0; e < 4; e++) {
                    h[e] = bhi(f[e]);
                    l[e] = bhi(f[e] - __bfloat162float(h[e]));
                }
                int row = j * 64 + xrow;
                __nv_bfloat162* ph = (__nv_bfloat162*)&Ah[d2][row * LDA + xq * 4];
                __nv_bfloat162* pl = (__nv_bfloat162*)&Al[d2][row * LDA + xq * 4];
                ph[0] = __halves2bfloat162(h[0], h[1]);
                ph[1] = __halves2bfloat162(h[2], h[3]);
                pl[0] = __halves2bfloat162(l[0], l[1]);
                pl[1] = __halves2bfloat162(l[2], l[3]);
            }
            conv_w_elem(Bh[d2], Bl[d2], tid, rw0);
            if (tid < 64) conv_w_elem(Bh[d2], Bl[d2], 256 + tid, rw1);

            if (s + 2 < NSTG) {
                load_x_regs(x4, mh, kbase + (s + 2) * KT, tid, rx);
                load_w_regs(w4, nh, kbase + (s + 2) * KT, tid, rw0, rw1);
            }
        }
        __syncthreads();
    }

    /* epilogue: partials [b][ks][n] */
    {
        float* base = g_Upart + (size_t)(mh * 128 + m0) * PSTRIDE + ks * NCOL + nh * 80;
        #pragma unroll
        for (int nt = 0; nt < 5; nt++)
            wmma::store_matrix_sync(base + nt * 16, c[nt], PSTRIDE, wmma::mem_row_major);
    }
}

/* ===== fused reduce (contiguous float4 stream) + collapsed routing ===== */
__global__ void __launch_bounds__(512)
routing_kernel(float* __restrict__ out) {
    const int b = blockIdx.x;
    const int t = threadIdx.x;

    __shared__ __align__(16) float red[12][NCOL];
    __shared__ float L[NUM_C];

    if (t < 480) {
        const float4* src = (const float4*)(g_Upart + (size_t)b * PSTRIDE);
        float4 s = make_float4(0.f, 0.f, 0.f, 0.f);
        #pragma unroll
        for (int j = 0; j < 3; j++) {
            float4 v = src[t + j * 480];
            s.x += v.x; s.y += v.y; s.z += v.z; s.w += v.w;
        }
        *(float4*)&red[t / 40][(t % 40) * 4] = s;
    }
    if (t < NUM_C) L[t] = 0.f;
    __syncthreads();

    const int cc = t >> 4;
    const int o  = t & 15;
    float u = 0.f, v = 0.f;
    if (t < NCOL) {
        #pragma unroll
        for (int i = 0; i < 12; i++) u += red[i][t];
    }

    for (int it = 0; it < 3; it++) {
        float p = 0.f, S = 0.f;
        if (t < NCOL) {
            float mx = L[0];
            #pragma unroll
            for (int j = 1; j < NUM_C; j++) mx = fmaxf(mx, L[j]);
            float den = 0.f;
            #pragma unroll
            for (int j = 0; j < NUM_C; j++) den += __expf(L[j] - mx);
            p = __expf(L[cc] - mx) / den;

            float tt = p * u;
            v = tt * fabsf(tt) / (1.f + tt * tt);

            S = v;
            S += __shfl_xor_sync(0xffffffffu, S, 8);
            S += __shfl_xor_sync(0xffffffffu, S, 4);
            S += __shfl_xor_sync(0xffffffffu, S, 2);
            S += __shfl_xor_sync(0xffffffffu, S, 1);
        }
        __syncthreads();
        if (t < NCOL && o == 0) L[cc] += p * S;
        __syncthreads();
    }
    if (t < NCOL) out[(size_t)b * NCOL + t] = v;
}

extern "C" void kernel_launch(void* const* d_in, const int* in_sizes, int n_in,
                              void* d_out, int out_size) {
    const float* x = (const float*)d_in[0];
    const float* w = (const float*)d_in[1];
    if (n_in >= 2 && in_sizes[0] == NUM_C * KDIM * OUT_CH) {
        w = (const float*)d_in[0];
        x = (const float*)d_in[1];
    }
    gemm_kernel<<<dim3(KSPLIT, 2, 2), NTHR>>>(x, w);
    routing_kernel<<<BATCH, 512>>>((float*)d_out);
    (void)out_size;
}

// round 8
// speedup vs baseline: 1.1963x; 1.1963x over previous
#include <cuda_runtime.h>
#include <cuda_bf16.h>
#include <mma.h>
#include <cstdint>
#include <math.h>

using namespace nvcuda;

#define NUM_C   10
#define OUT_CH  16
#define BATCH   256
#define KDIM    9216
#define NCOL    160

#define KSPLIT  72
#define KPER    128            /* K per block */
#define KT      16             /* K per stage */
#define NSTG    8
#define NTHR    128            /* 4 warps */
#define LDA     24             /* padded bf16 row (48B): LDSM conflict-free */
#define PSTRIDE (KSPLIT * NCOL)   /* 11520 */

/* partials: [b(256)][ks(72)][n(160)] — per-b contiguous for routing */
__device__ float g_Upart[BATCH * KSPLIT * NCOL];

/* packed fp32 -> bf16 hi/lo split: d_hi2 = [bf16(b):bf16(a)], d_lo2 = residuals */
__device__ __forceinline__ void cvt_split2(float a, float b,
                                           uint32_t& hi2, uint32_t& lo2) {
    asm("cvt.rn.bf16x2.f32 %0, %1, %2;" : "=r"(hi2) : "f"(b), "f"(a));
    float fa = __uint_as_float(hi2 << 16);
    float fb = __uint_as_float(hi2 & 0xFFFF0000u);
    float la = a - fa;
    float lb = b - fb;
    asm("cvt.rn.bf16x2.f32 %0, %1, %2;" : "=r"(lo2) : "f"(lb), "f"(la));
}

/* ============ GEMM: pipelined 3-pass bf16-split wmma, split-K ============ */
__global__ void __launch_bounds__(NTHR, 2)
gemm_kernel(const float* __restrict__ x, const float* __restrict__ w) {
    __shared__ __align__(16) __nv_bfloat16 Ah[2][128 * LDA];
    __shared__ __align__(16) __nv_bfloat16 Al[2][128 * LDA];
    __shared__ __align__(16) __nv_bfloat16 Bh[2][80 * LDA];
    __shared__ __align__(16) __nv_bfloat16 Bl[2][80 * LDA];

    const int tid  = threadIdx.x;
    const int warp = tid >> 5;
    const int ks   = blockIdx.x;
    const int nh   = blockIdx.y;
    const int mh   = blockIdx.z;
    const int kbase = ks * KPER;

    const float4* __restrict__ x4 = (const float4*)x;
    const float4* __restrict__ w4 = (const float4*)w;

    wmma::fragment<wmma::accumulator, 16, 16, 16, float> c[2][5];
    #pragma unroll
    for (int mt = 0; mt < 2; mt++)
        #pragma unroll
        for (int nt = 0; nt < 5; nt++) wmma::fill_fragment(c[mt][nt], 0.0f);

    float4 rx[4], rw[3];

    auto load_regs = [&](int k0) {
        #pragma unroll
        for (int j = 0; j < 4; j++) {
            int fid = j * NTHR + tid;
            int row = fid >> 2, xq = fid & 3;
            rx[j] = x4[(size_t)(mh * 128 + row) * (KDIM / 4) + (k0 >> 2) + xq];
        }
        #pragma unroll
        for (int j = 0; j < 3; j++) {
            if (j < 2 || tid < 64) {
                int fid = j * NTHR + tid;
                int cl = fid >> 6, rem = fid & 63;
                rw[j] = w4[((size_t)(nh * 5 + cl) * KDIM + k0 + (rem >> 2)) * 4 + (rem & 3)];
            }
        }
    };

    auto convert_store = [&](int d) {
        #pragma unroll
        for (int j = 0; j < 4; j++) {
            int fid = j * NTHR + tid;
            int row = fid >> 2, xq = fid & 3;
            uint32_t h0, l0, h1, l1;
            cvt_split2(rx[j].x, rx[j].y, h0, l0);
            cvt_split2(rx[j].z, rx[j].w, h1, l1);
            *(uint2*)&Ah[d][row * LDA + xq * 4] = make_uint2(h0, h1);
            *(uint2*)&Al[d][row * LDA + xq * 4] = make_uint2(l0, l1);
        }
        #pragma unroll
        for (int j = 0; j < 3; j++) {
            if (j < 2 || tid < 64) {
                int fid = j * NTHR + tid;
                int cl = fid >> 6, rem = fid & 63;
                int kloc = rem >> 2, o4 = rem & 3;
                int n0 = cl * 16 + o4 * 4;
                uint32_t hA, lA, hB, lB;
                cvt_split2(rw[j].x, rw[j].y, hA, lA);
                cvt_split2(rw[j].z, rw[j].w, hB, lB);
                uint16_t* bh = (uint16_t*)Bh[d];
                uint16_t* bl = (uint16_t*)Bl[d];
                bh[(n0 + 0) * LDA + kloc] = (uint16_t)(hA & 0xFFFFu);
                bh[(n0 + 1) * LDA + kloc] = (uint16_t)(hA >> 16);
                bh[(n0 + 2) * LDA + kloc] = (uint16_t)(hB & 0xFFFFu);
                bh[(n0 + 3) * LDA + kloc] = (uint16_t)(hB >> 16);
                bl[(n0 + 0) * LDA + kloc] = (uint16_t)(lA & 0xFFFFu);
                bl[(n0 + 1) * LDA + kloc] = (uint16_t)(lA >> 16);
                bl[(n0 + 2) * LDA + kloc] = (uint16_t)(lB & 0xFFFFu);
                bl[(n0 + 3) * LDA + kloc] = (uint16_t)(lB >> 16);
            }
        }
    };

    /* preamble: stage0 -> buf0, prefetch stage1 regs */
    load_regs(kbase);
    convert_store(0);
    load_regs(kbase + KT);
    __syncthreads();

    const int m0 = warp * 32;

    #pragma unroll
    for (int s = 0; s < NSTG; s++) {
        const int d = s & 1;
        {
            wmma::fragment<wmma::matrix_a, 16, 16, 16, __nv_bfloat16, wmma::row_major> ah0, ah1, al0, al1;
            wmma::load_matrix_sync(ah0, &Ah[d][m0 * LDA], LDA);
            wmma::load_matrix_sync(ah1, &Ah[d][(m0 + 16) * LDA], LDA);
            wmma::load_matrix_sync(al0, &Al[d][m0 * LDA], LDA);
            wmma::load_matrix_sync(al1, &Al[d][(m0 + 16) * LDA], LDA);
            wmma::fragment<wmma::matrix_b, 16, 16, 16, __nv_bfloat16, wmma::col_major> bh[5], bl[5];
            #pragma unroll
            for (int nt = 0; nt < 5; nt++) {
                wmma::load_matrix_sync(bh[nt], &Bh[d][nt * 16 * LDA], LDA);
                wmma::load_matrix_sync(bl[nt], &Bl[d][nt * 16 * LDA], LDA);
            }
            #pragma unroll
            for (int nt = 0; nt < 5; nt++) {
                wmma::mma_sync(c[0][nt], ah0, bh[nt], c[0][nt]);
                wmma::mma_sync(c[1][nt], ah1, bh[nt], c[1][nt]);
            }
            #pragma unroll
            for (int nt = 0; nt < 5; nt++) {
                wmma::mma_sync(c[0][nt], ah0, bl[nt], c[0][nt]);
                wmma::mma_sync(c[1][nt], ah1, bl[nt], c[1][nt]);
            }
            #pragma unroll
            for (int nt = 0; nt < 5; nt++) {
                wmma::mma_sync(c[0][nt], al0, bh[nt], c[0][nt]);
                wmma::mma_sync(c[1][nt], al1, bh[nt], c[1][nt]);
            }
        }
        if (s + 1 < NSTG) {
            convert_store(d ^ 1);
            if (s + 2 < NSTG) load_regs(kbase + (s + 2) * KT);
        }
        __syncthreads();
    }

    /* epilogue: partials [b][ks][n] */
    #pragma unroll
    for (int mt = 0; mt < 2; mt++)
        #pragma unroll
        for (int nt = 0; nt < 5; nt++)
            wmma::store_matrix_sync(
                g_Upart + (size_t)(mh * 128 + m0 + mt * 16) * PSTRIDE
                        + ks * NCOL + nh * 80 + nt * 16,
                c[mt][nt], PSTRIDE, wmma::mem_row_major);
}

/* ===== routing: 2 b's per block, single wave, 72-way reduce + 3-iter routing ===== */
__global__ void __launch_bounds__(1024)
routing_kernel(float* __restrict__ out) {
    const int t  = threadIdx.x;
    const int s  = t >> 9;            /* b-slot 0/1 */
    const int tt = t & 511;
    const int b  = blockIdx.x + s * 128;

    __shared__ __align__(16) float red[2][12][NCOL];
    __shared__ float L[2][NUM_C];

    if (tt < 480) {
        const float4* src = (const float4*)(g_Upart + (size_t)b * PSTRIDE);
        float4 a0 = src[tt];
        float4 a1 = src[tt + 480];
        float4 a2 = src[tt + 960];
        float4 a3 = src[tt + 1440];
        float4 a4 = src[tt + 1920];
        float4 a5 = src[tt + 2400];
        float4 acc;
        acc.x = ((a0.x + a1.x) + (a2.x + a3.x)) + (a4.x + a5.x);
        acc.y = ((a0.y + a1.y) + (a2.y + a3.y)) + (a4.y + a5.y);
        acc.z = ((a0.z + a1.z) + (a2.z + a3.z)) + (a4.z + a5.z);
        acc.w = ((a0.w + a1.w) + (a2.w + a3.w)) + (a4.w + a5.w);
        int pos = tt * 4;
        int ksl = pos / 160;
        int n   = pos % 160;
        *(float4*)&red[s][ksl][n] = acc;
    }
    if (tt < NUM_C) L[s][tt] = 0.f;
    __syncthreads();

    const int cc = tt >> 4;
    const int o  = tt & 15;
    float u = 0.f, v = 0.f;
    if (tt < NCOL) {
        float p0 = 0.f, p1 = 0.f, p2 = 0.f, p3 = 0.f;
        #pragma unroll
        for (int i = 0; i < 12; i += 4) {
            p0 += red[s][i][tt];
            p1 += red[s][i + 1][tt];
            p2 += red[s][i + 2][tt];
            p3 += red[s][i + 3][tt];
        }
        u = (p0 + p1) + (p2 + p3);
    }

    for (int it = 0; it < 3; it++) {
        float p = 0.f, S = 0.f;
        if (tt < NCOL) {
            float mx = L[s][0];
            #pragma unroll
            for (int j = 1; j < NUM_C; j++) mx = fmaxf(mx, L[s][j]);
            float den = 0.f;
            #pragma unroll
            for (int j = 0; j < NUM_C; j++) den += __expf(L[s][j] - mx);
            p = __expf(L[s][cc] - mx) / den;

            float tv = p * u;
            v = tv * fabsf(tv) / (1.f + tv * tv);

            S = v;
            S += __shfl_xor_sync(0xffffffffu, S, 8);
            S += __shfl_xor_sync(0xffffffffu, S, 4);
            S += __shfl_xor_sync(0xffffffffu, S, 2);
            S += __shfl_xor_sync(0xffffffffu, S, 1);
        }
        __syncthreads();
        if (tt < NCOL && o == 0) L[s][cc] += p * S;
        __syncthreads();
    }
    if (tt < NCOL) out[(size_t)b * NCOL + tt] = v;
}

extern "C" void kernel_launch(void* const* d_in, const int* in_sizes, int n_in,
                              void* d_out, int out_size) {
    const float* x = (const float*)d_in[0];
    const float* w = (const float*)d_in[1];
    if (n_in >= 2 && in_sizes[0] == NUM_C * KDIM * OUT_CH) {
        w = (const float*)d_in[0];
        x = (const float*)d_in[1];
    }
    gemm_kernel<<<dim3(KSPLIT, 2, 2), NTHR>>>(x, w);
    routing_kernel<<<BATCH / 2, 1024>>>((float*)d_out);
    (void)out_size;
}